// round 1
// baseline (speedup 1.0000x reference)
#include <cuda_runtime.h>
#include <cuda_bf16.h>
#include <math.h>

// Problem constants (fixed by the dataset problem)
#define BSZ   1024
#define TSEQ  64
#define IDIM  64
#define HDIM  1024
#define FUT   16
#define NSTEP (TSEQ + FUT)          // 80
#define G4H   (4 * HDIM)            // 4096
#define OUT_STRIDE (NSTEP * IDIM)   // 5120

// -------------------- scratch (device globals; no allocation) --------------------
__device__ float g_gates[BSZ * G4H];        // 16 MB gate pre-activations
__device__ float g_h1[BSZ * HDIM];
__device__ float g_c1[BSZ * HDIM];
__device__ float g_h2[BSZ * HDIM];
__device__ float g_c2[BSZ * HDIM];
__device__ float g_part[8 * BSZ * IDIM];    // split-K partials for head GEMM

// -------------------- init --------------------
__global__ void init_state_kernel() {
    int idx = blockIdx.x * blockDim.x + threadIdx.x;   // over BSZ*HDIM
    g_h1[idx] = 0.f; g_c1[idx] = 0.f;
    g_h2[idx] = 0.f; g_c2[idx] = 0.f;
}

// -------------------- fused two-operand gate GEMM --------------------
// gates[m, n] = sum_k A1[m,k] * W1[n,k]  (K1)
//            +  sum_k A2[m,k] * W2[n,k]  (K2)
//            +  ba[n] + bb[n]
// A operands selected by flag: 0 = external pointer, 1 = g_h1, 2 = g_h2.
// W matrices are (4H, K) row-major (K contiguous).
// Tile: 128(M) x 128(N) x 16(K); 256 threads, 8x8 per thread.
__global__ __launch_bounds__(256, 2)
void gemm_gates_kernel(const float* __restrict__ Aext, int lda1, int K1,
                       const float* __restrict__ W1,
                       int sel1, int sel2, int lda2, int K2,
                       const float* __restrict__ W2,
                       const float* __restrict__ ba, const float* __restrict__ bb)
{
    __shared__ float As[16][132];
    __shared__ float Ws[16][132];

    const int tid = threadIdx.x;
    const int tx  = tid & 15;       // 0..15  -> 8 cols each
    const int ty  = tid >> 4;       // 0..15  -> 8 rows each
    const int mBase = blockIdx.y * 128;
    const int nBase = blockIdx.x * 128;

    const int lr = tid >> 2;            // 0..63 (load row)
    const int lc = (tid & 3) << 2;      // 0,4,8,12 (load col, float4)

    float acc[8][8];
    #pragma unroll
    for (int i = 0; i < 8; ++i)
        #pragma unroll
        for (int j = 0; j < 8; ++j) acc[i][j] = 0.f;

    for (int phase = 0; phase < 2; ++phase) {
        const float* A;
        const float* W;
        int lda, K;
        if (phase == 0) {
            A = (sel1 == 0) ? Aext : ((sel1 == 1) ? g_h1 : g_h2);
            lda = lda1; K = K1; W = W1;
        } else {
            A = (sel2 == 1) ? g_h1 : g_h2;
            lda = lda2; K = K2; W = W2;
        }

        for (int k0 = 0; k0 < K; k0 += 16) {
            // load A tile (128 x 16) and W tile (128 x 16), float4 per thread x2
            #pragma unroll
            for (int it = 0; it < 2; ++it) {
                int row = lr + it * 64;
                float4 av = *reinterpret_cast<const float4*>(
                    &A[(size_t)(mBase + row) * lda + k0 + lc]);
                As[lc + 0][row] = av.x; As[lc + 1][row] = av.y;
                As[lc + 2][row] = av.z; As[lc + 3][row] = av.w;
                float4 wv = *reinterpret_cast<const float4*>(
                    &W[(size_t)(nBase + row) * K + k0 + lc]);
                Ws[lc + 0][row] = wv.x; Ws[lc + 1][row] = wv.y;
                Ws[lc + 2][row] = wv.z; Ws[lc + 3][row] = wv.w;
            }
            __syncthreads();

            #pragma unroll
            for (int kk = 0; kk < 16; ++kk) {
                float a[8], w[8];
                #pragma unroll
                for (int i = 0; i < 8; ++i) a[i] = As[kk][ty * 8 + i];
                #pragma unroll
                for (int j = 0; j < 8; ++j) w[j] = Ws[kk][tx * 8 + j];
                #pragma unroll
                for (int i = 0; i < 8; ++i)
                    #pragma unroll
                    for (int j = 0; j < 8; ++j)
                        acc[i][j] = fmaf(a[i], w[j], acc[i][j]);
            }
            __syncthreads();
        }
    }

    // epilogue: add biases, write gates
    #pragma unroll
    for (int i = 0; i < 8; ++i) {
        int m = mBase + ty * 8 + i;
        #pragma unroll
        for (int j = 0; j < 8; ++j) {
            int n = nBase + tx * 8 + j;
            g_gates[(size_t)m * G4H + n] = acc[i][j] + ba[n] + bb[n];
        }
    }
}

// -------------------- LSTM gate activation + state update --------------------
__global__ void lstm_act_kernel(int layer) {
    int idx = blockIdx.x * blockDim.x + threadIdx.x;   // over BSZ*HDIM
    int b = idx >> 10;       // HDIM = 1024
    int n = idx & 1023;
    const float* g = g_gates + (size_t)b * G4H;
    float xi = g[n];
    float xf = g[n + HDIM];
    float xg = g[n + 2 * HDIM];
    float xo = g[n + 3 * HDIM];

    float gi = 1.f / (1.f + expf(-xi));
    float gf = 1.f / (1.f + expf(-xf));
    float gg = tanhf(xg);
    float go = 1.f / (1.f + expf(-xo));

    float* hbuf = (layer == 1) ? g_h1 : g_h2;
    float* cbuf = (layer == 1) ? g_c1 : g_c2;
    float cn = gf * cbuf[idx] + gi * gg;
    cbuf[idx] = cn;
    hbuf[idx] = go * tanhf(cn);
}

// -------------------- head GEMM: out = h2 @ W_lin^T + b_lin --------------------
// Stage 1: split-K partials. Grid (16 m-tiles, 8 k-chunks). Tile 64x64, K-chunk 128.
__global__ __launch_bounds__(256)
void lin_stage1_kernel(const float* __restrict__ Wlin) {
    __shared__ float Hs[16][68];
    __shared__ float Ws[16][68];

    const int tid = threadIdx.x;
    const int mBase = blockIdx.x * 64;
    const int ks = blockIdx.y;               // 0..7
    const int kBeg = ks * 128;

    const int lr = tid >> 2;                 // 0..63
    const int lc = (tid & 3) << 2;           // 0,4,8,12
    const int tx = tid & 15;                 // 4 cols each
    const int ty = tid >> 4;                 // 4 rows each

    float acc[4][4];
    #pragma unroll
    for (int i = 0; i < 4; ++i)
        #pragma unroll
        for (int j = 0; j < 4; ++j) acc[i][j] = 0.f;

    for (int k0 = kBeg; k0 < kBeg + 128; k0 += 16) {
        float4 hv = *reinterpret_cast<const float4*>(
            &g_h2[(size_t)(mBase + lr) * HDIM + k0 + lc]);
        Hs[lc + 0][lr] = hv.x; Hs[lc + 1][lr] = hv.y;
        Hs[lc + 2][lr] = hv.z; Hs[lc + 3][lr] = hv.w;
        float4 wv = *reinterpret_cast<const float4*>(
            &Wlin[(size_t)lr * HDIM + k0 + lc]);
        Ws[lc + 0][lr] = wv.x; Ws[lc + 1][lr] = wv.y;
        Ws[lc + 2][lr] = wv.z; Ws[lc + 3][lr] = wv.w;
        __syncthreads();

        #pragma unroll
        for (int kk = 0; kk < 16; ++kk) {
            float a[4], w[4];
            #pragma unroll
            for (int i = 0; i < 4; ++i) a[i] = Hs[kk][ty * 4 + i];
            #pragma unroll
            for (int j = 0; j < 4; ++j) w[j] = Ws[kk][tx * 4 + j];
            #pragma unroll
            for (int i = 0; i < 4; ++i)
                #pragma unroll
                for (int j = 0; j < 4; ++j)
                    acc[i][j] = fmaf(a[i], w[j], acc[i][j]);
        }
        __syncthreads();
    }

    #pragma unroll
    for (int i = 0; i < 4; ++i) {
        int m = mBase + ty * 4 + i;
        #pragma unroll
        for (int j = 0; j < 4; ++j) {
            int n = tx * 4 + j;
            g_part[(size_t)ks * (BSZ * IDIM) + m * IDIM + n] = acc[i][j];
        }
    }
}

// Stage 2: deterministic reduce over 8 partials + bias; write to strided d_out slice.
__global__ void lin_stage2_kernel(const float* __restrict__ blin,
                                  float* __restrict__ outp) {
    int idx = blockIdx.x * blockDim.x + threadIdx.x;   // over BSZ*IDIM
    int m = idx >> 6;
    int n = idx & 63;
    float s = blin[n];
    #pragma unroll
    for (int ks = 0; ks < 8; ++ks) s += g_part[ks * (BSZ * IDIM) + idx];
    outp[(size_t)m * OUT_STRIDE + n] = s;
}

// -------------------- launch --------------------
extern "C" void kernel_launch(void* const* d_in, const int* in_sizes, int n_in,
                              void* d_out, int out_size) {
    const float* x     = (const float*)d_in[0];
    const float* W_ih1 = (const float*)d_in[1];
    const float* W_hh1 = (const float*)d_in[2];
    const float* b_ih1 = (const float*)d_in[3];
    const float* b_hh1 = (const float*)d_in[4];
    const float* W_ih2 = (const float*)d_in[5];
    const float* W_hh2 = (const float*)d_in[6];
    const float* b_ih2 = (const float*)d_in[7];
    const float* b_hh2 = (const float*)d_in[8];
    const float* W_lin = (const float*)d_in[9];
    const float* b_lin = (const float*)d_in[10];
    float* out = (float*)d_out;

    init_state_kernel<<<(BSZ * HDIM) / 256, 256>>>();

    const dim3 gGrid(G4H / 128, BSZ / 128);     // (32, 8)
    const int  actBlocks = (BSZ * HDIM) / 256;  // 4096

    for (int s = 0; s < NSTEP; ++s) {
        const float* a1;
        int lda1;
        if (s < TSEQ) { a1 = x + (size_t)s * IDIM;             lda1 = TSEQ * IDIM; }
        else          { a1 = out + (size_t)(s - 1) * IDIM;     lda1 = OUT_STRIDE; }

        // layer 1: gates = x_t @ W_ih1^T + h1 @ W_hh1^T + b
        gemm_gates_kernel<<<gGrid, 256>>>(a1, lda1, IDIM, W_ih1,
                                          0, 1, HDIM, HDIM, W_hh1,
                                          b_ih1, b_hh1);
        lstm_act_kernel<<<actBlocks, 256>>>(1);

        // layer 2: gates = h1 @ W_ih2^T + h2 @ W_hh2^T + b
        gemm_gates_kernel<<<gGrid, 256>>>(nullptr, HDIM, HDIM, W_ih2,
                                          1, 2, HDIM, HDIM, W_hh2,
                                          b_ih2, b_hh2);
        lstm_act_kernel<<<actBlocks, 256>>>(2);

        // head: out_s = h2 @ W_lin^T + b_lin
        lin_stage1_kernel<<<dim3(BSZ / 64, 8), 256>>>(W_lin);
        lin_stage2_kernel<<<(BSZ * IDIM) / 256, 256>>>(b_lin, out + (size_t)s * IDIM);
    }
}

// round 3
// speedup vs baseline: 2.5996x; 2.5996x over previous
#include <cuda_runtime.h>
#include <cuda_bf16.h>
#include <cstdint>
#include <math.h>

#define BSZ   1024
#define TSEQ  64
#define IDIM  64
#define HDIM  1024
#define FUT   16
#define NSTEP (TSEQ + FUT)          // 80
#define G4H   (4 * HDIM)            // 4096
#define OUT_STRIDE (NSTEP * IDIM)   // 5120

typedef __nv_bfloat16 bf16;

// ---------------- device scratch (static; no runtime allocation) ----------------
__device__ bf16 g_wih1_h[G4H * IDIM],  g_wih1_l[G4H * IDIM];
__device__ bf16 g_whh1_h[G4H * HDIM],  g_whh1_l[G4H * HDIM];
__device__ bf16 g_wih2_h[G4H * HDIM],  g_wih2_l[G4H * HDIM];
__device__ bf16 g_whh2_h[G4H * HDIM],  g_whh2_l[G4H * HDIM];
__device__ float g_bias1[G4H], g_bias2[G4H];
__device__ bf16 g_x_h[BSZ * TSEQ * IDIM], g_x_l[BSZ * TSEQ * IDIM];
__device__ bf16 g_h1_h[2][BSZ * HDIM], g_h1_l[2][BSZ * HDIM];
__device__ bf16 g_h2_h[2][BSZ * HDIM], g_h2_l[2][BSZ * HDIM];
__device__ float g_c1[BSZ * HDIM], g_c2[BSZ * HDIM];
__device__ bf16 g_fb_h[BSZ * IDIM], g_fb_l[BSZ * IDIM];   // autoregressive feedback
__device__ float g_part[8 * BSZ * IDIM];                  // head split-K partials

// ---------------- helpers ----------------
__device__ __forceinline__ uint32_t smem_u32(const void* p) {
    return (uint32_t)__cvta_generic_to_shared(p);
}
__device__ __forceinline__ void cp16(uint32_t dst, const void* src) {
    asm volatile("cp.async.cg.shared.global [%0], [%1], 16;\n" :: "r"(dst), "l"(src));
}
__device__ __forceinline__ void cp_commit() { asm volatile("cp.async.commit_group;\n"); }
template<int N> __device__ __forceinline__ void cp_wait() {
    asm volatile("cp.async.wait_group %0;\n" :: "n"(N));
}
__device__ __forceinline__ void ldsm4(uint32_t* r, uint32_t a) {
    asm volatile("ldmatrix.sync.aligned.m8n8.x4.shared.b16 {%0,%1,%2,%3}, [%4];"
        : "=r"(r[0]), "=r"(r[1]), "=r"(r[2]), "=r"(r[3]) : "r"(a));
}
__device__ __forceinline__ void mma16816(float* d, const uint32_t* a, uint32_t b0, uint32_t b1) {
    asm volatile("mma.sync.aligned.m16n8k16.row.col.f32.bf16.bf16.f32 "
        "{%0,%1,%2,%3}, {%4,%5,%6,%7}, {%8,%9}, {%0,%1,%2,%3};"
        : "+f"(d[0]), "+f"(d[1]), "+f"(d[2]), "+f"(d[3])
        : "r"(a[0]), "r"(a[1]), "r"(a[2]), "r"(a[3]), "r"(b0), "r"(b1));
}
#define SWZ(x) ((x) ^ (((x) >> 3) & 0x70))

__device__ __forceinline__ float sigm(float x) { return 1.f / (1.f + __expf(-x)); }
__device__ __forceinline__ float tanh_f(float x) { return 2.f / (1.f + __expf(-2.f * x)) - 1.f; }
__device__ __forceinline__ void split2(float v, bf16& hi, bf16& lo) {
    hi = __float2bfloat16(v);
    lo = __float2bfloat16(v - __bfloat162float(hi));
}

// ---------------- prepass kernels ----------------
// Gate-permuting weight split: row n (gate g = n/1024, unit u = n%1024) -> row u*4+g
__global__ void prep_w_perm(const float* __restrict__ src, bf16* __restrict__ dh,
                            bf16* __restrict__ dl, int K) {
    size_t e = ((size_t)blockIdx.x * blockDim.x + threadIdx.x) * 4;
    int n = (int)(e / K);
    int k = (int)(e % K);
    int pn = ((n & 1023) << 2) | (n >> 10);
    float4 v = *(const float4*)(src + e);
    float vv[4] = {v.x, v.y, v.z, v.w};
    #pragma unroll
    for (int j = 0; j < 4; ++j) {
        bf16 hi, lo; split2(vv[j], hi, lo);
        dh[(size_t)pn * K + k + j] = hi;
        dl[(size_t)pn * K + k + j] = lo;
    }
}
__global__ void prep_split(const float* __restrict__ src, bf16* __restrict__ dh,
                           bf16* __restrict__ dl) {
    size_t e = ((size_t)blockIdx.x * blockDim.x + threadIdx.x) * 4;
    float4 v = *(const float4*)(src + e);
    float vv[4] = {v.x, v.y, v.z, v.w};
    #pragma unroll
    for (int j = 0; j < 4; ++j) {
        bf16 hi, lo; split2(vv[j], hi, lo);
        dh[e + j] = hi; dl[e + j] = lo;
    }
}
__global__ void prep_bias(const float* b1a, const float* b1b,
                          const float* b2a, const float* b2b) {
    int n = blockIdx.x * blockDim.x + threadIdx.x;   // 0..4095
    int pn = ((n & 1023) << 2) | (n >> 10);
    g_bias1[pn] = b1a[n] + b1b[n];
    g_bias2[pn] = b2a[n] + b2b[n];
}
__global__ void init_state() {
    int i = blockIdx.x * blockDim.x + threadIdx.x;   // over BSZ*HDIM
    bf16 z = __float2bfloat16(0.f);
    g_h1_h[0][i] = z; g_h1_l[0][i] = z;
    g_h2_h[0][i] = z; g_h2_l[0][i] = z;
    g_c1[i] = 0.f; g_c2[i] = 0.f;
}

// ---------------- main LSTM layer kernel (mma.sync bf16 hi/lo 3-term) ----------------
// C tile 128(M) x 128(N gate cols). Two A phases: nA chunks of (A1,W1), nB of (A2,W2).
// K-chunk = 64 bf16 (128B rows, SW128 swizzle). Fused LSTM epilogue.
#define STAGE 65536   // Ah 16K | Al 16K | Wh 16K | Wl 16K

__global__ void __launch_bounds__(256, 1)
gemm_lstm(const bf16* __restrict__ A1h, const bf16* __restrict__ A1l, int s1, int nA,
          const bf16* __restrict__ A2h, const bf16* __restrict__ A2l, int s2, int nB,
          const bf16* __restrict__ W1h, const bf16* __restrict__ W1l, int w1s,
          const bf16* __restrict__ W2h, const bf16* __restrict__ W2l, int w2s,
          const float* __restrict__ bias,
          float* __restrict__ cbuf, bf16* __restrict__ Hh, bf16* __restrict__ Hl)
{
    extern __shared__ __align__(1024) char smem[];
    const int tid = threadIdx.x;
    const int mBase = blockIdx.y * 128;
    const int nBase = blockIdx.x * 128;
    const uint32_t sb = smem_u32(smem);

    float* sbias = (float*)(smem + 3 * STAGE);
    if (tid < 128) sbias[tid] = bias[nBase + tid];

    const int C = nA + nB;

    auto load_chunk = [&](int c, int st) {
        const bf16 *Ah, *Al, *Wh, *Wl; int as, ws;
        if (c < nA) { Ah = A1h + c * 64; Al = A1l + c * 64; as = s1;
                      Wh = W1h + c * 64; Wl = W1l + c * 64; ws = w1s; }
        else        { int d = c - nA;
                      Ah = A2h + d * 64; Al = A2l + d * 64; as = s2;
                      Wh = W2h + d * 64; Wl = W2l + d * 64; ws = w2s; }
        uint32_t base = sb + st * STAGE;
        #pragma unroll
        for (int j = 0; j < 4; ++j) {
            int o = tid + j * 256; int row = o >> 3; int eo = (o & 7) * 8;
            uint32_t boff = SWZ(row * 128 + eo * 2);
            cp16(base + boff,         Ah + (size_t)(mBase + row) * as + eo);
            cp16(base + 16384 + boff, Al + (size_t)(mBase + row) * as + eo);
            cp16(base + 32768 + boff, Wh + (size_t)(nBase + row) * ws + eo);
            cp16(base + 49152 + boff, Wl + (size_t)(nBase + row) * ws + eo);
        }
        cp_commit();
    };

    // warp mapping: 8 warps = 4(m) x 2(n); warp tile 32 x 64
    const int w = tid >> 5, l = tid & 31;
    const int wm = (w & 3) * 32, wn = (w >> 2) * 64;

    float acc[2][8][4];
    #pragma unroll
    for (int mt = 0; mt < 2; ++mt)
        #pragma unroll
        for (int nt = 0; nt < 8; ++nt)
            #pragma unroll
            for (int j = 0; j < 4; ++j) acc[mt][nt][j] = 0.f;

    load_chunk(0, 0);
    load_chunk(1, 1);
    load_chunk(2, 2);

    // precompute lane-dependent relative offsets (per ks added later)
    const int aRowOff[2] = { (wm + 0 * 16 + (l & 15)) << 7, (wm + 1 * 16 + (l & 15)) << 7 };
    const int aColSub = (l >> 4) << 4;                        // 0 or 16
    int wRowOff[4];
    #pragma unroll
    for (int ng = 0; ng < 4; ++ng)
        wRowOff[ng] = (wn + ng * 16 + (l & 7) + (((l >> 4) & 1) << 3)) << 7;
    const int wColSub = ((l >> 3) & 1) << 4;                  // 0 or 16

    for (int c = 0; c < C; ++c) {
        const int st = c % 3;
        cp_wait<2>();
        __syncthreads();

        const uint32_t bAh = sb + st * STAGE;
        const uint32_t bAl = bAh + 16384;
        const uint32_t bWh = bAh + 32768;
        const uint32_t bWl = bAh + 49152;

        #pragma unroll
        for (int ks = 0; ks < 4; ++ks) {
            uint32_t ah[2][4], al[2][4], wh[4][4], wl[4][4];
            #pragma unroll
            for (int mt = 0; mt < 2; ++mt) {
                uint32_t off = SWZ((uint32_t)(aRowOff[mt] + ks * 32 + aColSub));
                ldsm4(ah[mt], bAh + off);
                ldsm4(al[mt], bAl + off);
            }
            #pragma unroll
            for (int ng = 0; ng < 4; ++ng) {
                uint32_t off = SWZ((uint32_t)(wRowOff[ng] + ks * 32 + wColSub));
                ldsm4(wh[ng], bWh + off);
                ldsm4(wl[ng], bWl + off);
            }
            #pragma unroll
            for (int mt = 0; mt < 2; ++mt) {
                #pragma unroll
                for (int ng = 0; ng < 4; ++ng) {
                    mma16816(acc[mt][ng * 2],     ah[mt], wh[ng][0], wh[ng][1]);
                    mma16816(acc[mt][ng * 2],     ah[mt], wl[ng][0], wl[ng][1]);
                    mma16816(acc[mt][ng * 2],     al[mt], wh[ng][0], wh[ng][1]);
                    mma16816(acc[mt][ng * 2 + 1], ah[mt], wh[ng][2], wh[ng][3]);
                    mma16816(acc[mt][ng * 2 + 1], ah[mt], wl[ng][2], wl[ng][3]);
                    mma16816(acc[mt][ng * 2 + 1], al[mt], wh[ng][2], wh[ng][3]);
                }
            }
        }
        __syncthreads();
        if (c + 3 < C) load_chunk(c + 3, (c + 3) % 3);
        else cp_commit();   // keep group count aligned with wait<2>
    }

    // ---------------- fused LSTM epilogue ----------------
    const int gr = l >> 2;
    const bool odd = l & 1;
    const int q = (l >> 1) & 1;

    #pragma unroll
    for (int mt = 0; mt < 2; ++mt) {
        #pragma unroll
        for (int nt = 0; nt < 8; ++nt) {
            float c0 = acc[mt][nt][0], c1 = acc[mt][nt][1];
            float c2 = acc[mt][nt][2], c3 = acc[mt][nt][3];
            float sx = odd ? c0 : c2;
            float sy = odd ? c1 : c3;
            float rx = __shfl_xor_sync(0xFFFFFFFFu, sx, 1);
            float ry = __shfl_xor_sync(0xFFFFFFFFu, sy, 1);
            float iv, fv, gv, ov;
            if (!odd) { iv = c0; fv = c1; gv = rx; ov = ry; }
            else      { iv = rx; fv = ry; gv = c2; ov = c3; }
            int nn  = wn + nt * 8 + q * 4;           // CTA-local gate-i column
            int row = mBase + wm + mt * 16 + gr + (odd ? 8 : 0);
            float xi = iv + sbias[nn + 0];
            float xf = fv + sbias[nn + 1];
            float xg = gv + sbias[nn + 2];
            float xo = ov + sbias[nn + 3];
            float gi = sigm(xi), gf = sigm(xf), gg = tanh_f(xg), go = sigm(xo);
            int unit = (nBase + nn) >> 2;
            size_t idx = (size_t)row * HDIM + unit;
            float cn = gf * cbuf[idx] + gi * gg;
            cbuf[idx] = cn;
            float hn = go * tanh_f(cn);
            bf16 hi, lo; split2(hn, hi, lo);
            Hh[idx] = hi; Hl[idx] = lo;
        }
    }
}

// ---------------- head GEMM: out = h2 @ W_lin^T + b_lin (fp32 split-K) ----------------
__global__ __launch_bounds__(256)
void lin_stage1_kernel(const bf16* __restrict__ Hh, const bf16* __restrict__ Hl,
                       const float* __restrict__ Wlin) {
    __shared__ float Hs[16][68];
    __shared__ float Ws[16][68];

    const int tid = threadIdx.x;
    const int mBase = blockIdx.x * 64;
    const int ks = blockIdx.y;               // 0..7
    const int kBeg = ks * 128;

    const int lr = tid >> 2;
    const int lc = (tid & 3) << 2;
    const int tx = tid & 15;
    const int ty = tid >> 4;

    float acc[4][4];
    #pragma unroll
    for (int i = 0; i < 4; ++i)
        #pragma unroll
        for (int j = 0; j < 4; ++j) acc[i][j] = 0.f;

    for (int k0 = kBeg; k0 < kBeg + 128; k0 += 16) {
        size_t hoff = (size_t)(mBase + lr) * HDIM + k0 + lc;
        const __nv_bfloat162* ph = (const __nv_bfloat162*)(Hh + hoff);
        const __nv_bfloat162* pl = (const __nv_bfloat162*)(Hl + hoff);
        float2 h0 = __bfloat1622float2(ph[0]);
        float2 h1 = __bfloat1622float2(ph[1]);
        float2 l0 = __bfloat1622float2(pl[0]);
        float2 l1 = __bfloat1622float2(pl[1]);
        Hs[lc + 0][lr] = h0.x + l0.x; Hs[lc + 1][lr] = h0.y + l0.y;
        Hs[lc + 2][lr] = h1.x + l1.x; Hs[lc + 3][lr] = h1.y + l1.y;
        float4 wv = *reinterpret_cast<const float4*>(&Wlin[(size_t)lr * HDIM + k0 + lc]);
        Ws[lc + 0][lr] = wv.x; Ws[lc + 1][lr] = wv.y;
        Ws[lc + 2][lr] = wv.z; Ws[lc + 3][lr] = wv.w;
        __syncthreads();

        #pragma unroll
        for (int kk = 0; kk < 16; ++kk) {
            float a[4], wv2[4];
            #pragma unroll
            for (int i = 0; i < 4; ++i) a[i] = Hs[kk][ty * 4 + i];
            #pragma unroll
            for (int j = 0; j < 4; ++j) wv2[j] = Ws[kk][tx * 4 + j];
            #pragma unroll
            for (int i = 0; i < 4; ++i)
                #pragma unroll
                for (int j = 0; j < 4; ++j)
                    acc[i][j] = fmaf(a[i], wv2[j], acc[i][j]);
        }
        __syncthreads();
    }

    #pragma unroll
    for (int i = 0; i < 4; ++i) {
        int m = mBase + ty * 4 + i;
        #pragma unroll
        for (int j = 0; j < 4; ++j) {
            int n = tx * 4 + j;
            g_part[(size_t)ks * (BSZ * IDIM) + m * IDIM + n] = acc[i][j];
        }
    }
}

__global__ void lin_stage2_kernel(const float* __restrict__ blin,
                                  float* __restrict__ outp) {
    int idx = blockIdx.x * blockDim.x + threadIdx.x;   // over BSZ*IDIM
    int m = idx >> 6;
    int n = idx & 63;
    float s = blin[n];
    #pragma unroll
    for (int ks = 0; ks < 8; ++ks) s += g_part[ks * (BSZ * IDIM) + idx];
    outp[(size_t)m * OUT_STRIDE + n] = s;
    bf16 hi, lo; split2(s, hi, lo);
    g_fb_h[idx] = hi; g_fb_l[idx] = lo;
}

// ---------------- host launch ----------------
extern "C" void kernel_launch(void* const* d_in, const int* in_sizes, int n_in,
                              void* d_out, int out_size) {
    const float* x     = (const float*)d_in[0];
    const float* W_ih1 = (const float*)d_in[1];
    const float* W_hh1 = (const float*)d_in[2];
    const float* b_ih1 = (const float*)d_in[3];
    const float* b_hh1 = (const float*)d_in[4];
    const float* W_ih2 = (const float*)d_in[5];
    const float* W_hh2 = (const float*)d_in[6];
    const float* b_ih2 = (const float*)d_in[7];
    const float* b_hh2 = (const float*)d_in[8];
    const float* W_lin = (const float*)d_in[9];
    const float* b_lin = (const float*)d_in[10];
    float* out = (float*)d_out;

    void *wih1h, *wih1l, *whh1h, *whh1l, *wih2h, *wih2l, *whh2h, *whh2l;
    void *xh, *xl, *h1h, *h1l, *h2h, *h2l, *c1, *c2, *fbh, *fbl, *bias1, *bias2;
    cudaGetSymbolAddress(&wih1h, g_wih1_h); cudaGetSymbolAddress(&wih1l, g_wih1_l);
    cudaGetSymbolAddress(&whh1h, g_whh1_h); cudaGetSymbolAddress(&whh1l, g_whh1_l);
    cudaGetSymbolAddress(&wih2h, g_wih2_h); cudaGetSymbolAddress(&wih2l, g_wih2_l);
    cudaGetSymbolAddress(&whh2h, g_whh2_h); cudaGetSymbolAddress(&whh2l, g_whh2_l);
    cudaGetSymbolAddress(&xh, g_x_h);       cudaGetSymbolAddress(&xl, g_x_l);
    cudaGetSymbolAddress(&h1h, g_h1_h);     cudaGetSymbolAddress(&h1l, g_h1_l);
    cudaGetSymbolAddress(&h2h, g_h2_h);     cudaGetSymbolAddress(&h2l, g_h2_l);
    cudaGetSymbolAddress(&c1, g_c1);        cudaGetSymbolAddress(&c2, g_c2);
    cudaGetSymbolAddress(&fbh, g_fb_h);     cudaGetSymbolAddress(&fbl, g_fb_l);
    cudaGetSymbolAddress(&bias1, g_bias1);  cudaGetSymbolAddress(&bias2, g_bias2);

    bf16* H1h[2] = { (bf16*)h1h, (bf16*)h1h + BSZ * HDIM };
    bf16* H1l[2] = { (bf16*)h1l, (bf16*)h1l + BSZ * HDIM };
    bf16* H2h[2] = { (bf16*)h2h, (bf16*)h2h + BSZ * HDIM };
    bf16* H2l[2] = { (bf16*)h2l, (bf16*)h2l + BSZ * HDIM };

    constexpr int SMEM_MAIN = 3 * STAGE + 512;   // 197120
    cudaFuncSetAttribute(gemm_lstm, cudaFuncAttributeMaxDynamicSharedMemorySize, SMEM_MAIN);

    // ---- prepasses ----
    prep_w_perm<<<4096, 256>>>(W_hh1, (bf16*)whh1h, (bf16*)whh1l, HDIM);
    prep_w_perm<<<4096, 256>>>(W_ih2, (bf16*)wih2h, (bf16*)wih2l, HDIM);
    prep_w_perm<<<4096, 256>>>(W_hh2, (bf16*)whh2h, (bf16*)whh2l, HDIM);
    prep_w_perm<<<256, 256>>>(W_ih1, (bf16*)wih1h, (bf16*)wih1l, IDIM);
    prep_split<<<4096, 256>>>(x, (bf16*)xh, (bf16*)xl);
    prep_bias<<<16, 256>>>(b_ih1, b_hh1, b_ih2, b_hh2);
    init_state<<<4096, 256>>>();

    const dim3 gL(G4H / 128, BSZ / 128);   // (32, 8)

    for (int s = 0; s < NSTEP; ++s) {
        int rp = s & 1, wp = rp ^ 1;

        const bf16 *a1h, *a1l; int s1;
        if (s < TSEQ) { a1h = (const bf16*)xh + (size_t)s * IDIM;
                        a1l = (const bf16*)xl + (size_t)s * IDIM; s1 = TSEQ * IDIM; }
        else          { a1h = (const bf16*)fbh; a1l = (const bf16*)fbl; s1 = IDIM; }

        gemm_lstm<<<gL, 256, SMEM_MAIN>>>(
            a1h, a1l, s1, 1,
            H1h[rp], H1l[rp], HDIM, 16,
            (const bf16*)wih1h, (const bf16*)wih1l, IDIM,
            (const bf16*)whh1h, (const bf16*)whh1l, HDIM,
            (const float*)bias1,
            (float*)c1, H1h[wp], H1l[wp]);

        gemm_lstm<<<gL, 256, SMEM_MAIN>>>(
            H1h[wp], H1l[wp], HDIM, 16,
            H2h[rp], H2l[rp], HDIM, 16,
            (const bf16*)wih2h, (const bf16*)wih2l, HDIM,
            (const bf16*)whh2h, (const bf16*)whh2l, HDIM,
            (const float*)bias2,
            (float*)c2, H2h[wp], H2l[wp]);

        lin_stage1_kernel<<<dim3(BSZ / 64, 8), 256>>>(H2h[wp], H2l[wp], W_lin);
        lin_stage2_kernel<<<(BSZ * IDIM) / 256, 256>>>(b_lin, out + (size_t)s * IDIM);
    }
}